// round 7
// baseline (speedup 1.0000x reference)
#include <cuda_runtime.h>
#include <cuda_bf16.h>

#define NN   50000
#define NE   800000
#define HID  96
#define NREL 3
#define NG   512
#define CLS  16
#define GR   128                              // GEMM rows per block

#define SCAN_B 1024
#define NBLK   ((NN + SCAN_B - 1) / SCAN_B)   // 49

// ---------------- scratch (alloc-free rule: device globals) ----------------
__device__ int      g_is64;                  // 1 if inputs are int64, 0 if int32
__device__ unsigned g_esrc[NE];              // src | (r<<16)   (NN < 2^16)
__device__ int      g_edst[NE];              // dst
__device__ int      g_batch[NN];             // graph id per node
__device__ float    g_agg[NREL * NN * HID];  // per-relation mean of x[src] by dst
__device__ float    g_cnt[NREL * NN];        // deg_r(dst) as float
__device__ int      g_deg[NN];               // total in-degree
__device__ int      g_cursor[NN];
__device__ int      g_rowstart[NN + 1];
__device__ int      g_bsum[NBLK];
__device__ int      g_boff[NBLK];
__device__ unsigned g_elist[NE];             // CSR-ordered src | (r<<16)
__device__ float    g_h1[NN * HID];
__device__ float    g_h2[NN * HID];
__device__ float    g_pool[NG * HID];        // per-graph MEAN (already divided)

// ---------------- dtype detection ----------------
// If edge_index is int64 (values < 2^31), every odd int32 word is 0.
__global__ void k_detect(const int* __restrict__ ei32) {
    if (threadIdx.x == 0 && blockIdx.x == 0) {
        int any_odd_nonzero = 0;
        for (int i = 0; i < 64; i++)
            if (ei32[2 * i + 1] != 0) any_odd_nonzero = 1;
        g_is64 = any_odd_nonzero ? 0 : 1;
    }
}

// ---------------- canonicalize indices to int32 + zero counters ----------------
__global__ void k_cvt(const int* __restrict__ ei32,
                      const int* __restrict__ et32,
                      const int* __restrict__ ba32) {
    int i = blockIdx.x * blockDim.x + threadIdx.x;
    int is64 = g_is64;
    if (i < NE) {
        int s, d, r;
        if (is64) {
            s = ei32[2 * i];
            d = ei32[2 * (NE + i)];
            r = et32[2 * i];
        } else {
            s = ei32[i];
            d = ei32[NE + i];
            r = et32[i];
        }
        g_esrc[i] = (unsigned)s | ((unsigned)r << 16);
        g_edst[i] = d;
    }
    if (i < NN) {
        g_batch[i]  = is64 ? ba32[2 * i] : ba32[i];
        g_deg[i]    = 0;
        g_cursor[i] = 0;
    }
    if (i < NREL * NN) g_cnt[i] = 0.f;
}

// ---------------- degree counts ----------------
__global__ void k_count() {
    int e = blockIdx.x * blockDim.x + threadIdx.x;
    if (e >= NE) return;
    int d = g_edst[e];
    int r = (int)(g_esrc[e] >> 16);
    atomicAdd(&g_cnt[r * NN + d], 1.0f);
    atomicAdd(&g_deg[d], 1);
}

// ---------------- 3-kernel exclusive scan over g_deg ----------------
__global__ __launch_bounds__(SCAN_B) void k_scanA() {
    __shared__ int sh[SCAN_B];
    int i = blockIdx.x * SCAN_B + threadIdx.x;
    int v = (i < NN) ? g_deg[i] : 0;
    sh[threadIdx.x] = v;
    __syncthreads();
    for (int off = 1; off < SCAN_B; off <<= 1) {
        int t = (threadIdx.x >= off) ? sh[threadIdx.x - off] : 0;
        __syncthreads();
        sh[threadIdx.x] += t;
        __syncthreads();
    }
    if (i < NN) g_rowstart[i] = sh[threadIdx.x] - v;   // block-local exclusive
    if (threadIdx.x == SCAN_B - 1) g_bsum[blockIdx.x] = sh[threadIdx.x];
}

__global__ void k_scanB() {
    if (threadIdx.x == 0 && blockIdx.x == 0) {
        int acc = 0;
        for (int b = 0; b < NBLK; b++) { g_boff[b] = acc; acc += g_bsum[b]; }
        g_rowstart[NN] = acc;   // == NE
    }
}

__global__ void k_scanC() {
    int i = blockIdx.x * blockDim.x + threadIdx.x;
    if (i < NN) g_rowstart[i] += g_boff[i / SCAN_B];
}

// ---------------- CSR fill ----------------
__global__ void k_fill() {
    int e = blockIdx.x * blockDim.x + threadIdx.x;
    if (e >= NE) return;
    int d = g_edst[e];
    int pos = g_rowstart[d] + atomicAdd(&g_cursor[d], 1);
    g_elist[pos] = g_esrc[e];
}

// ---------------- gather-aggregate (input space, one warp per dst) ----------
// agg_r[dst] = mean_{src in N_r(dst)} X[src]   -> g_agg[r][dst][:]
// 4-edge unroll: ~12 payload LDGs in flight per warp -> latency/MLP_eff small.
__global__ __launch_bounds__(256) void k_agg(const float* __restrict__ Xin,
                                             int layer) {
    const float* X = layer ? g_h1 : Xin;
    int w    = (blockIdx.x * blockDim.x + threadIdx.x) >> 5;
    int lane = threadIdx.x & 31;
    if (w >= NN) return;

    int beg = g_rowstart[w];
    int end = g_rowstart[w + 1];

    float s00 = 0.f, s01 = 0.f, s02 = 0.f;   // relation 0
    float s10 = 0.f, s11 = 0.f, s12 = 0.f;   // relation 1
    float s20 = 0.f, s21 = 0.f, s22 = 0.f;   // relation 2

    int e = beg;
    for (; e + 3 < end; e += 4) {
        unsigned p0 = __ldg(&g_elist[e]);
        unsigned p1 = __ldg(&g_elist[e + 1]);
        unsigned p2 = __ldg(&g_elist[e + 2]);
        unsigned p3 = __ldg(&g_elist[e + 3]);
        const float* ha = X + (size_t)(p0 & 0xFFFFu) * HID;
        const float* hb = X + (size_t)(p1 & 0xFFFFu) * HID;
        const float* hc = X + (size_t)(p2 & 0xFFFFu) * HID;
        const float* hd = X + (size_t)(p3 & 0xFFFFu) * HID;
        float a0 = ha[lane], a1 = ha[lane + 32], a2 = ha[lane + 64];
        float b0 = hb[lane], b1 = hb[lane + 32], b2 = hb[lane + 64];
        float c0 = hc[lane], c1 = hc[lane + 32], c2 = hc[lane + 64];
        float d0 = hd[lane], d1 = hd[lane + 32], d2 = hd[lane + 64];
        unsigned r0 = p0 >> 16, r1 = p1 >> 16, r2 = p2 >> 16, r3 = p3 >> 16;
        if (r0 == 0)      { s00 += a0; s01 += a1; s02 += a2; }
        else if (r0 == 1) { s10 += a0; s11 += a1; s12 += a2; }
        else              { s20 += a0; s21 += a1; s22 += a2; }
        if (r1 == 0)      { s00 += b0; s01 += b1; s02 += b2; }
        else if (r1 == 1) { s10 += b0; s11 += b1; s12 += b2; }
        else              { s20 += b0; s21 += b1; s22 += b2; }
        if (r2 == 0)      { s00 += c0; s01 += c1; s02 += c2; }
        else if (r2 == 1) { s10 += c0; s11 += c1; s12 += c2; }
        else              { s20 += c0; s21 += c1; s22 += c2; }
        if (r3 == 0)      { s00 += d0; s01 += d1; s02 += d2; }
        else if (r3 == 1) { s10 += d0; s11 += d1; s12 += d2; }
        else              { s20 += d0; s21 += d1; s22 += d2; }
    }
    for (; e < end; e++) {
        unsigned p0 = __ldg(&g_elist[e]);
        const float* ha = X + (size_t)(p0 & 0xFFFFu) * HID;
        float a0 = ha[lane], a1 = ha[lane + 32], a2 = ha[lane + 64];
        unsigned r0 = p0 >> 16;
        if (r0 == 0)      { s00 += a0; s01 += a1; s02 += a2; }
        else if (r0 == 1) { s10 += a0; s11 += a1; s12 += a2; }
        else              { s20 += a0; s21 += a1; s22 += a2; }
    }

    float inv0 = 1.0f / fmaxf(g_cnt[w],          1.0f);
    float inv1 = 1.0f / fmaxf(g_cnt[NN + w],     1.0f);
    float inv2 = 1.0f / fmaxf(g_cnt[2 * NN + w], 1.0f);

    size_t o = (size_t)w * HID;
    g_agg[o + lane]      = s00 * inv0;
    g_agg[o + lane + 32] = s01 * inv0;
    g_agg[o + lane + 64] = s02 * inv0;
    g_agg[(size_t)NN * HID + o + lane]      = s10 * inv1;
    g_agg[(size_t)NN * HID + o + lane + 32] = s11 * inv1;
    g_agg[(size_t)NN * HID + o + lane + 64] = s12 * inv1;
    g_agg[(size_t)2 * NN * HID + o + lane]      = s20 * inv2;
    g_agg[(size_t)2 * NN * HID + o + lane + 32] = s21 * inv2;
    g_agg[(size_t)2 * NN * HID + o + lane + 64] = s22 * inv2;
}

// ---------------- fused 4-way GEMM + bias + relu (8x4 register tile) -------
// h[i] = relu( X[i]@Wroot + b + sum_r agg_r[i]@Wrel[r] )
// Block: 384 threads cover a 128x96 output tile.
//   cg = tid % 24  -> output cols cg*4 .. cg*4+3
//   rg = tid / 24  -> output rows rg*8 .. rg*8+7   (rg 0..15)
// Smem/FMA = 48B per warp-FFMA (X reads are warp-broadcast) -> FFMA-issue bound.
__global__ __launch_bounds__(384) void k_gemm(const float* __restrict__ Xin,
                                              const float* __restrict__ Wrel,
                                              const float* __restrict__ Wroot,
                                              const float* __restrict__ bias,
                                              int layer) {
    extern __shared__ float sm[];
    float* Ws = sm;                 // HID*HID = 9216 floats (36 KB)
    float* Xs = sm + HID * HID;     // GR*HID = 12288 floats (48 KB)
    const float* X    = layer ? g_h1 : Xin;
    float*       Hout = layer ? g_h2 : g_h1;

    int row0 = blockIdx.x * GR;
    int cg = threadIdx.x % 24;
    int rg = threadIdx.x / 24;
    int c0 = cg * 4;

    float acc[8][4];
    {
        float4 bb = *(const float4*)&bias[c0];
#pragma unroll
        for (int j = 0; j < 8; j++) {
            acc[j][0] = bb.x; acc[j][1] = bb.y; acc[j][2] = bb.z; acc[j][3] = bb.w;
        }
    }

    for (int st = 0; st < 4; st++) {
        const float* W   = (st == 0) ? Wroot : (Wrel + (size_t)(st - 1) * HID * HID);
        const float* src = (st == 0) ? X     : (g_agg + (size_t)(st - 1) * NN * HID);

        if (st) __syncthreads();   // previous stage done reading smem
        for (int i = threadIdx.x; i < HID * HID; i += 384) Ws[i] = W[i];
        for (int i = threadIdx.x; i < GR * HID; i += 384) {
            int gr = row0 + i / HID;
            Xs[i] = (gr < NN) ? src[(size_t)gr * HID + (i % HID)] : 0.f;
        }
        __syncthreads();

#pragma unroll 4
        for (int k = 0; k < HID; k += 4) {
            float4 wv0 = *(const float4*)&Ws[(k + 0) * HID + c0];
            float4 wv1 = *(const float4*)&Ws[(k + 1) * HID + c0];
            float4 wv2 = *(const float4*)&Ws[(k + 2) * HID + c0];
            float4 wv3 = *(const float4*)&Ws[(k + 3) * HID + c0];
#pragma unroll
            for (int j = 0; j < 8; j++) {
                float4 xv = *(const float4*)&Xs[(rg * 8 + j) * HID + k];
                acc[j][0] += xv.x * wv0.x; acc[j][1] += xv.x * wv0.y;
                acc[j][2] += xv.x * wv0.z; acc[j][3] += xv.x * wv0.w;
                acc[j][0] += xv.y * wv1.x; acc[j][1] += xv.y * wv1.y;
                acc[j][2] += xv.y * wv1.z; acc[j][3] += xv.y * wv1.w;
                acc[j][0] += xv.z * wv2.x; acc[j][1] += xv.z * wv2.y;
                acc[j][2] += xv.z * wv2.z; acc[j][3] += xv.z * wv2.w;
                acc[j][0] += xv.w * wv3.x; acc[j][1] += xv.w * wv3.y;
                acc[j][2] += xv.w * wv3.z; acc[j][3] += xv.w * wv3.w;
            }
        }
    }

#pragma unroll
    for (int j = 0; j < 8; j++) {
        int gr = row0 + rg * 8 + j;
        if (gr < NN) {
            float4 v;
            v.x = fmaxf(acc[j][0], 0.f);
            v.y = fmaxf(acc[j][1], 0.f);
            v.z = fmaxf(acc[j][2], 0.f);
            v.w = fmaxf(acc[j][3], 0.f);
            *(float4*)&Hout[(size_t)gr * HID + c0] = v;
        }
    }
}

// ---------------- deterministic graph mean pool ----------------
// g_batch is SORTED. One block per graph: binary-search node range, reduce.
__global__ __launch_bounds__(HID) void k_pool() {
    int g = blockIdx.x;
    int lo = 0, hi = NN;
    while (lo < hi) { int m = (lo + hi) >> 1; if (g_batch[m] < g) lo = m + 1; else hi = m; }
    int lo2 = lo, hi2 = NN;
    while (lo2 < hi2) { int m = (lo2 + hi2) >> 1; if (g_batch[m] < g + 1) lo2 = m + 1; else hi2 = m; }

    int c = threadIdx.x;          // 0..95, coalesced across the row
    float s = 0.f;
    for (int n = lo; n < lo2; n++)
        s += g_h2[(size_t)n * HID + c];
    g_pool[g * HID + c] = s / fmaxf((float)(lo2 - lo), 1.0f);
}

// ---------------- final linear head ----------------
__global__ void k_final(const float* __restrict__ Wlin,
                        const float* __restrict__ blin,
                        float* __restrict__ out) {
    __shared__ float Ws[HID * CLS];
    for (int i = threadIdx.x; i < HID * CLS; i += blockDim.x) Ws[i] = Wlin[i];
    __syncthreads();
    int i = blockIdx.x * blockDim.x + threadIdx.x;
    if (i >= NG * CLS) return;
    int g = i / CLS, k = i % CLS;
    float acc = blin[k];
#pragma unroll
    for (int c = 0; c < HID; c++)
        acc += g_pool[g * HID + c] * Ws[c * CLS + k];
    out[i] = acc;
}

// ---------------- launch ----------------
extern "C" void kernel_launch(void* const* d_in, const int* in_sizes, int n_in,
                              void* d_out, int out_size) {
    const float* x     = (const float*)d_in[0];
    const int*   ei32  = (const int*)d_in[1];    // int32 or int64 (detected)
    const int*   et32  = (const int*)d_in[2];
    const int*   ba32  = (const int*)d_in[3];
    const float* Wrel1 = (const float*)d_in[4];
    const float* Wroot1= (const float*)d_in[5];
    const float* b1    = (const float*)d_in[6];
    const float* Wrel2 = (const float*)d_in[7];
    const float* Wroot2= (const float*)d_in[8];
    const float* b2    = (const float*)d_in[9];
    const float* Wlin  = (const float*)d_in[10];
    const float* blin  = (const float*)d_in[11];
    float*       out   = (float*)d_out;

    const int ZB = 256;
    const int GSM = (HID * HID + GR * HID) * (int)sizeof(float);  // 86016 B
    cudaFuncSetAttribute(k_gemm, cudaFuncAttributeMaxDynamicSharedMemorySize, GSM);
    int ggrid = (NN + GR - 1) / GR;

    // ---- dtype detection + canonicalization + CSR build ----
    k_detect<<<1, 32>>>(ei32);
    k_cvt  <<<(NE + ZB - 1) / ZB, ZB>>>(ei32, et32, ba32);
    k_count<<<(NE + ZB - 1) / ZB, ZB>>>();
    k_scanA<<<NBLK, SCAN_B>>>();
    k_scanB<<<1, 32>>>();
    k_scanC<<<(NN + ZB - 1) / ZB, ZB>>>();
    k_fill <<<(NE + ZB - 1) / ZB, ZB>>>();

    // ---- layer 1 ----
    k_agg <<<(NN * 32 + ZB - 1) / ZB, ZB>>>(x, 0);
    k_gemm<<<ggrid, 384, GSM>>>(x, Wrel1, Wroot1, b1, 0);

    // ---- layer 2 ----
    k_agg <<<(NN * 32 + ZB - 1) / ZB, ZB>>>(x, 1);
    k_gemm<<<ggrid, 384, GSM>>>(x, Wrel2, Wroot2, b2, 1);

    // ---- pool + head ----
    k_pool <<<NG, HID>>>();
    k_final<<<(NG * CLS + ZB - 1) / ZB, ZB>>>(Wlin, blin, out);
}

// round 10
// speedup vs baseline: 1.0859x; 1.0859x over previous
#include <cuda_runtime.h>
#include <cuda_bf16.h>

#define NN   50000
#define NE   800000
#define HID  96
#define NREL 3
#define NG   512
#define CLS  16
#define GR   64                               // GEMM rows per block
#define GT   192                              // GEMM threads per block

#define SCAN_B 1024
#define NBLK   ((NN + SCAN_B - 1) / SCAN_B)   // 49

// ---------------- scratch (alloc-free rule: device globals) ----------------
__device__ unsigned g_esrc[NE];              // src | (r<<16)   (NN < 2^16)
__device__ int      g_edst[NE];              // dst
__device__ int      g_batch[NN];             // graph id per node
__device__ float    g_agg[NREL * NN * HID];  // per-relation mean of x[src] by dst
__device__ float    g_cnt[NREL * NN];        // deg_r(dst) as float
__device__ int      g_deg[NN];               // total in-degree
__device__ int      g_cursor[NN];
__device__ int      g_rowstart[NN + 1];
__device__ int      g_bsum[NBLK];
__device__ unsigned g_elist[NE];             // CSR-ordered src | (r<<16)
__device__ float    g_h1[NN * HID];
__device__ float    g_h2[NN * HID];
__device__ float    g_pool[NG * HID];        // per-graph MEAN (already divided)

// ---------------- zero counters (must precede k_cvt's atomics) -------------
__global__ void k_zero() {
    int i = blockIdx.x * blockDim.x + threadIdx.x;
    if (i < NREL * NN) g_cnt[i] = 0.f;
    if (i < NN) { g_deg[i] = 0; g_cursor[i] = 0; }
}

// ---- canonicalize indices (int64/int32 auto-detect) + count ---------------
// Detection: for int64 data with values < 2^31, every odd int32 word is 0.
__global__ void k_cvt(const int* __restrict__ ei32,
                      const int* __restrict__ et32,
                      const int* __restrict__ ba32) {
    int pred = 0;
    if (threadIdx.x < 64) pred = (ei32[2 * threadIdx.x + 1] != 0);
    int is32 = __syncthreads_or(pred);       // any odd word nonzero -> int32
    int i = blockIdx.x * blockDim.x + threadIdx.x;

    if (i < NE) {
        int s, d, r;
        if (is32) {
            s = ei32[i];
            d = ei32[NE + i];
            r = et32[i];
        } else {
            s = ei32[2 * i];
            d = ei32[2 * (NE + i)];
            r = et32[2 * i];
        }
        g_esrc[i] = (unsigned)s | ((unsigned)r << 16);
        g_edst[i] = d;
        atomicAdd(&g_cnt[r * NN + d], 1.0f);
        atomicAdd(&g_deg[d], 1);
    }
    if (i < NN) g_batch[i] = is32 ? ba32[i] : ba32[2 * i];
}

// ---------------- exclusive scan over g_deg (2 kernels) ----------------
__global__ __launch_bounds__(SCAN_B) void k_scanA() {
    __shared__ int sh[SCAN_B];
    int i = blockIdx.x * SCAN_B + threadIdx.x;
    int v = (i < NN) ? g_deg[i] : 0;
    sh[threadIdx.x] = v;
    __syncthreads();
    for (int off = 1; off < SCAN_B; off <<= 1) {
        int t = (threadIdx.x >= off) ? sh[threadIdx.x - off] : 0;
        __syncthreads();
        sh[threadIdx.x] += t;
        __syncthreads();
    }
    if (i < NN) g_rowstart[i] = sh[threadIdx.x] - v;   // block-local exclusive
    if (threadIdx.x == SCAN_B - 1) g_bsum[blockIdx.x] = sh[threadIdx.x];
}

// Adds per-block prefix (NBLK=49: each thread loops; broadcast L1 hits).
// The i==NN thread writes the grand total (scanA never wrote rowstart[NN]).
__global__ void k_scanC() {
    int i = blockIdx.x * blockDim.x + threadIdx.x;
    if (i > NN) return;
    int nb = (i == NN) ? NBLK : (i / SCAN_B);
    int acc = 0;
    for (int b = 0; b < nb; b++) acc += g_bsum[b];
    if (i == NN) g_rowstart[NN] = acc;       // == NE
    else         g_rowstart[i] += acc;
}

// ---------------- CSR fill ----------------
__global__ void k_fill() {
    int e = blockIdx.x * blockDim.x + threadIdx.x;
    if (e >= NE) return;
    int d = g_edst[e];
    int pos = g_rowstart[d] + atomicAdd(&g_cursor[d], 1);
    g_elist[pos] = g_esrc[e];
}

// ---------------- gather-aggregate (input space, one warp per dst) ----------
// agg_r[dst] = mean_{src in N_r(dst)} X[src]   -> g_agg[r][dst][:]
// 4-edge unroll: ~12 payload LDGs in flight per warp.
__global__ __launch_bounds__(256) void k_agg(const float* __restrict__ Xin,
                                             int layer) {
    const float* X = layer ? g_h1 : Xin;
    int w    = (blockIdx.x * blockDim.x + threadIdx.x) >> 5;
    int lane = threadIdx.x & 31;
    if (w >= NN) return;

    int beg = g_rowstart[w];
    int end = g_rowstart[w + 1];

    float s00 = 0.f, s01 = 0.f, s02 = 0.f;
    float s10 = 0.f, s11 = 0.f, s12 = 0.f;
    float s20 = 0.f, s21 = 0.f, s22 = 0.f;

    int e = beg;
    for (; e + 3 < end; e += 4) {
        unsigned p0 = __ldg(&g_elist[e]);
        unsigned p1 = __ldg(&g_elist[e + 1]);
        unsigned p2 = __ldg(&g_elist[e + 2]);
        unsigned p3 = __ldg(&g_elist[e + 3]);
        const float* ha = X + (size_t)(p0 & 0xFFFFu) * HID;
        const float* hb = X + (size_t)(p1 & 0xFFFFu) * HID;
        const float* hc = X + (size_t)(p2 & 0xFFFFu) * HID;
        const float* hd = X + (size_t)(p3 & 0xFFFFu) * HID;
        float a0 = ha[lane], a1 = ha[lane + 32], a2 = ha[lane + 64];
        float b0 = hb[lane], b1 = hb[lane + 32], b2 = hb[lane + 64];
        float c0 = hc[lane], c1 = hc[lane + 32], c2 = hc[lane + 64];
        float d0 = hd[lane], d1 = hd[lane + 32], d2 = hd[lane + 64];
        unsigned r0 = p0 >> 16, r1 = p1 >> 16, r2 = p2 >> 16, r3 = p3 >> 16;
        if (r0 == 0)      { s00 += a0; s01 += a1; s02 += a2; }
        else if (r0 == 1) { s10 += a0; s11 += a1; s12 += a2; }
        else              { s20 += a0; s21 += a1; s22 += a2; }
        if (r1 == 0)      { s00 += b0; s01 += b1; s02 += b2; }
        else if (r1 == 1) { s10 += b0; s11 += b1; s12 += b2; }
        else              { s20 += b0; s21 += b1; s22 += b2; }
        if (r2 == 0)      { s00 += c0; s01 += c1; s02 += c2; }
        else if (r2 == 1) { s10 += c0; s11 += c1; s12 += c2; }
        else              { s20 += c0; s21 += c1; s22 += c2; }
        if (r3 == 0)      { s00 += d0; s01 += d1; s02 += d2; }
        else if (r3 == 1) { s10 += d0; s11 += d1; s12 += d2; }
        else              { s20 += d0; s21 += d1; s22 += d2; }
    }
    for (; e < end; e++) {
        unsigned p0 = __ldg(&g_elist[e]);
        const float* ha = X + (size_t)(p0 & 0xFFFFu) * HID;
        float a0 = ha[lane], a1 = ha[lane + 32], a2 = ha[lane + 64];
        unsigned r0 = p0 >> 16;
        if (r0 == 0)      { s00 += a0; s01 += a1; s02 += a2; }
        else if (r0 == 1) { s10 += a0; s11 += a1; s12 += a2; }
        else              { s20 += a0; s21 += a1; s22 += a2; }
    }

    float inv0 = 1.0f / fmaxf(g_cnt[w],          1.0f);
    float inv1 = 1.0f / fmaxf(g_cnt[NN + w],     1.0f);
    float inv2 = 1.0f / fmaxf(g_cnt[2 * NN + w], 1.0f);

    size_t o = (size_t)w * HID;
    g_agg[o + lane]      = s00 * inv0;
    g_agg[o + lane + 32] = s01 * inv0;
    g_agg[o + lane + 64] = s02 * inv0;
    g_agg[(size_t)NN * HID + o + lane]      = s10 * inv1;
    g_agg[(size_t)NN * HID + o + lane + 32] = s11 * inv1;
    g_agg[(size_t)NN * HID + o + lane + 64] = s12 * inv1;
    g_agg[(size_t)2 * NN * HID + o + lane]      = s20 * inv2;
    g_agg[(size_t)2 * NN * HID + o + lane + 32] = s21 * inv2;
    g_agg[(size_t)2 * NN * HID + o + lane + 64] = s22 * inv2;
}

// ---------------- fused 4-way GEMM + bias + relu (8x4 register tile) -------
// h[i] = relu( X[i]@Wroot + b + sum_r agg_r[i]@Wrel[r] )
// Block: 192 threads cover a 64x96 output tile (782 tiles, 3 CTAs/SM at 60KB
// smem -> 444 slots -> wave-quantization factor 1.14).
//   cg = tid % 24 -> output cols cg*4..+3 ; rg = tid / 24 -> rows rg*8..+7
__global__ __launch_bounds__(GT) void k_gemm(const float* __restrict__ Xin,
                                             const float* __restrict__ Wrel,
                                             const float* __restrict__ Wroot,
                                             const float* __restrict__ bias,
                                             int layer) {
    extern __shared__ float sm[];
    float* Ws = sm;                 // HID*HID = 9216 floats (36 KB)
    float* Xs = sm + HID * HID;     // GR*HID  = 6144 floats (24 KB)
    const float* X    = layer ? g_h1 : Xin;
    float*       Hout = layer ? g_h2 : g_h1;

    int row0 = blockIdx.x * GR;
    int cg = threadIdx.x % 24;
    int rg = threadIdx.x / 24;      // 0..7
    int c0 = cg * 4;

    float acc[8][4];
    {
        float4 bb = *(const float4*)&bias[c0];
#pragma unroll
        for (int j = 0; j < 8; j++) {
            acc[j][0] = bb.x; acc[j][1] = bb.y; acc[j][2] = bb.z; acc[j][3] = bb.w;
        }
    }

    for (int st = 0; st < 4; st++) {
        const float* W   = (st == 0) ? Wroot : (Wrel + (size_t)(st - 1) * HID * HID);
        const float* src = (st == 0) ? X     : (g_agg + (size_t)(st - 1) * NN * HID);

        if (st) __syncthreads();   // previous stage done reading smem
        for (int i = threadIdx.x; i < HID * HID; i += GT) Ws[i] = W[i];
        for (int i = threadIdx.x; i < GR * HID; i += GT) {
            int gr = row0 + i / HID;
            Xs[i] = (gr < NN) ? src[(size_t)gr * HID + (i % HID)] : 0.f;
        }
        __syncthreads();

#pragma unroll 4
        for (int k = 0; k < HID; k += 4) {
            float4 wv0 = *(const float4*)&Ws[(k + 0) * HID + c0];
            float4 wv1 = *(const float4*)&Ws[(k + 1) * HID + c0];
            float4 wv2 = *(const float4*)&Ws[(k + 2) * HID + c0];
            float4 wv3 = *(const float4*)&Ws[(k + 3) * HID + c0];
#pragma unroll
            for (int j = 0; j < 8; j++) {
                float4 xv = *(const float4*)&Xs[(rg * 8 + j) * HID + k];
                acc[j][0] += xv.x * wv0.x; acc[j][1] += xv.x * wv0.y;
                acc[j][2] += xv.x * wv0.z; acc[j][3] += xv.x * wv0.w;
                acc[j][0] += xv.y * wv1.x; acc[j][1] += xv.y * wv1.y;
                acc[j][2] += xv.y * wv1.z; acc[j][3] += xv.y * wv1.w;
                acc[j][0] += xv.z * wv2.x; acc[j][1] += xv.z * wv2.y;
                acc[j][2] += xv.z * wv2.z; acc[j][3] += xv.z * wv2.w;
                acc[j][0] += xv.w * wv3.x; acc[j][1] += xv.w * wv3.y;
                acc[j][2] += xv.w * wv3.z; acc[j][3] += xv.w * wv3.w;
            }
        }
    }

#pragma unroll
    for (int j = 0; j < 8; j++) {
        int gr = row0 + rg * 8 + j;
        if (gr < NN) {
            float4 v;
            v.x = fmaxf(acc[j][0], 0.f);
            v.y = fmaxf(acc[j][1], 0.f);
            v.z = fmaxf(acc[j][2], 0.f);
            v.w = fmaxf(acc[j][3], 0.f);
            *(float4*)&Hout[(size_t)gr * HID + c0] = v;
        }
    }
}

// ---------------- deterministic graph mean pool ----------------
// g_batch is SORTED. One block per graph: binary-search node range, reduce.
__global__ __launch_bounds__(HID) void k_pool() {
    int g = blockIdx.x;
    int lo = 0, hi = NN;
    while (lo < hi) { int m = (lo + hi) >> 1; if (g_batch[m] < g) lo = m + 1; else hi = m; }
    int lo2 = lo, hi2 = NN;
    while (lo2 < hi2) { int m = (lo2 + hi2) >> 1; if (g_batch[m] < g + 1) lo2 = m + 1; else hi2 = m; }

    int c = threadIdx.x;          // 0..95, coalesced across the row
    float s = 0.f;
    for (int n = lo; n < lo2; n++)
        s += g_h2[(size_t)n * HID + c];
    g_pool[g * HID + c] = s / fmaxf((float)(lo2 - lo), 1.0f);
}

// ---------------- final linear head ----------------
__global__ void k_final(const float* __restrict__ Wlin,
                        const float* __restrict__ blin,
                        float* __restrict__ out) {
    __shared__ float Ws[HID * CLS];
    for (int i = threadIdx.x; i < HID * CLS; i += blockDim.x) Ws[i] = Wlin[i];
    __syncthreads();
    int i = blockIdx.x * blockDim.x + threadIdx.x;
    if (i >= NG * CLS) return;
    int g = i / CLS, k = i % CLS;
    float acc = blin[k];
#pragma unroll
    for (int c = 0; c < HID; c++)
        acc += g_pool[g * HID + c] * Ws[c * CLS + k];
    out[i] = acc;
}

// ---------------- launch ----------------
extern "C" void kernel_launch(void* const* d_in, const int* in_sizes, int n_in,
                              void* d_out, int out_size) {
    const float* x     = (const float*)d_in[0];
    const int*   ei32  = (const int*)d_in[1];    // int32 or int64 (detected)
    const int*   et32  = (const int*)d_in[2];
    const int*   ba32  = (const int*)d_in[3];
    const float* Wrel1 = (const float*)d_in[4];
    const float* Wroot1= (const float*)d_in[5];
    const float* b1    = (const float*)d_in[6];
    const float* Wrel2 = (const float*)d_in[7];
    const float* Wroot2= (const float*)d_in[8];
    const float* b2    = (const float*)d_in[9];
    const float* Wlin  = (const float*)d_in[10];
    const float* blin  = (const float*)d_in[11];
    float*       out   = (float*)d_out;

    const int ZB = 256;
    const int GSM = (HID * HID + GR * HID) * (int)sizeof(float);  // 61440 B
    cudaFuncSetAttribute(k_gemm, cudaFuncAttributeMaxDynamicSharedMemorySize, GSM);
    int ggrid = (NN + GR - 1) / GR;

    // Launch order fixes ncu (-s 5 -c 1) onto k_agg (launch #6):
    //   zero(1) cvt(2) scanA(3) scanC(4) fill(5) agg(6)
    k_zero <<<(NREL * NN + ZB - 1) / ZB, ZB>>>();
    k_cvt  <<<(NE + ZB - 1) / ZB, ZB>>>(ei32, et32, ba32);
    k_scanA<<<NBLK, SCAN_B>>>();
    k_scanC<<<(NN + 1 + ZB - 1) / ZB, ZB>>>();
    k_fill <<<(NE + ZB - 1) / ZB, ZB>>>();

    // ---- layer 1 ----
    k_agg <<<(NN * 32 + ZB - 1) / ZB, ZB>>>(x, 0);
    k_gemm<<<ggrid, GT, GSM>>>(x, Wrel1, Wroot1, b1, 0);

    // ---- layer 2 ----
    k_agg <<<(NN * 32 + ZB - 1) / ZB, ZB>>>(x, 1);
    k_gemm<<<ggrid, GT, GSM>>>(x, Wrel2, Wroot2, b2, 1);

    // ---- pool + head ----
    k_pool <<<NG, HID>>>();
    k_final<<<(NG * CLS + ZB - 1) / ZB, ZB>>>(Wlin, blin, out);
}